// round 3
// baseline (speedup 1.0000x reference)
#include <cuda_runtime.h>
#include <math.h>

// Problem capacities (actual sizes derived from in_sizes at launch)
#define MAXN 50000
#define MAXETOT 850000   // E + N self loops

// ---------------- scratch (static __device__, no allocation) ----------------
__device__ int   g_deg[MAXN];
__device__ int   g_off[MAXN + 1];
__device__ int   g_cur[MAXN];
__device__ int   g_srcl[MAXETOT];
__device__ float g_dinv[MAXN];

__device__ float g_h1 [MAXN * 256];   // layer1 linear output  [N,8,32]
__device__ float g_as1[MAXN * 8];
__device__ float g_ad1[MAXN * 8];
__device__ float g_h1e[MAXN * 256];   // elu(gat1 out)
__device__ float g_h2 [MAXN * 16];    // layer2 linear output
__device__ float g_as2[MAXN];
__device__ float g_ad2[MAXN];
__device__ float g_h3 [MAXN * 16];    // elu(gat2 out) @ W3   (GCN is linear -> fold W3 early)

__device__ __forceinline__ float lrelu(float x) { return x > 0.f ? x : 0.2f * x; }
__device__ __forceinline__ float elu_f(float x) { return x > 0.f ? x : expm1f(x); }

// ---------------- CSR build ----------------
__global__ void k_zero_deg(int N) {
    int i = blockIdx.x * blockDim.x + threadIdx.x;
    if (i < N) g_deg[i] = 0;
}

__global__ void k_hist(const int* __restrict__ ei, int E, int N) {
    int e = blockIdx.x * blockDim.x + threadIdx.x;
    int Etot = E + N;
    if (e >= Etot) return;
    int d = (e < E) ? ei[E + e] : (e - E);   // dst row of edge_index, then self loops
    atomicAdd(&g_deg[d], 1);
}

__global__ void k_scan(int N, int Etot) {
    __shared__ int sums[1024];
    int t = threadIdx.x;
    int chunk = (N + 1023) >> 10;
    int b = t * chunk;
    int e = min(b + chunk, N);
    int s = 0;
    for (int i = b; i < e; i++) s += g_deg[i];
    sums[t] = s;
    __syncthreads();
    // inclusive Hillis-Steele
    for (int o = 1; o < 1024; o <<= 1) {
        int v = (t >= o) ? sums[t - o] : 0;
        __syncthreads();
        sums[t] += v;
        __syncthreads();
    }
    int base = (t > 0) ? sums[t - 1] : 0;
    for (int i = b; i < e; i++) {
        int d = g_deg[i];
        g_off[i] = base;
        g_cur[i] = base;
        g_dinv[i] = rsqrtf((float)d);   // self-loop guarantees d >= 1
        base += d;
    }
    if (t == 0) g_off[N] = Etot;
}

__global__ void k_fill(const int* __restrict__ ei, int E, int N) {
    int e = blockIdx.x * blockDim.x + threadIdx.x;
    int Etot = E + N;
    if (e >= Etot) return;
    int s, d;
    if (e < E) { s = ei[e]; d = ei[E + e]; }
    else       { s = e - E; d = e - E; }
    int pos = atomicAdd(&g_cur[d], 1);
    g_srcl[pos] = s;
}

// ---------------- GEMM1: h1 = x @ W1   (M x 128) @ (128 x 256) ----------------
#define BM 64
#define BN 64
#define BKK 16
__global__ void k_gemm1(const float* __restrict__ A, const float* __restrict__ B, int M) {
    __shared__ float As[BKK][BM];
    __shared__ float Bs[BKK][BN];
    const int Kd = 128, Nd = 256;
    int tx = threadIdx.x & 15, ty = threadIdx.x >> 4;
    int rowBase = blockIdx.y * BM, colBase = blockIdx.x * BN;
    float acc[4][4] = {};
    for (int k0 = 0; k0 < Kd; k0 += BKK) {
        for (int i = threadIdx.x; i < BM * BKK; i += 256) {
            int m = i >> 4, kk = i & 15;
            int gr = rowBase + m;
            As[kk][m] = (gr < M) ? A[gr * Kd + k0 + kk] : 0.f;
        }
        for (int i = threadIdx.x; i < BKK * BN; i += 256) {
            int kk = i >> 6, n = i & 63;
            Bs[kk][n] = B[(k0 + kk) * Nd + colBase + n];
        }
        __syncthreads();
#pragma unroll
        for (int kk = 0; kk < BKK; kk++) {
            float a[4], b[4];
#pragma unroll
            for (int i = 0; i < 4; i++) a[i] = As[kk][ty * 4 + i];
#pragma unroll
            for (int j = 0; j < 4; j++) b[j] = Bs[kk][tx * 4 + j];
#pragma unroll
            for (int i = 0; i < 4; i++)
#pragma unroll
                for (int j = 0; j < 4; j++) acc[i][j] += a[i] * b[j];
        }
        __syncthreads();
    }
#pragma unroll
    for (int i = 0; i < 4; i++) {
        int gr = rowBase + ty * 4 + i;
        if (gr >= M) continue;
        float4 v = make_float4(acc[i][0], acc[i][1], acc[i][2], acc[i][3]);
        *(float4*)(g_h1 + gr * Nd + colBase + tx * 4) = v;
    }
}

// ---------------- alpha1: per-node attention logits (warp per node) ----------------
__global__ void k_alpha1(const float* __restrict__ a_src1, const float* __restrict__ a_dst1, int N) {
    int w = (blockIdx.x * blockDim.x + threadIdx.x) >> 5;
    int lane = threadIdx.x & 31;
    if (w >= N) return;
    const float4* hp = (const float4*)(g_h1 + w * 256 + lane * 8);
    float4 v0 = hp[0], v1 = hp[1];
    int h = lane >> 2;
    int base = h * 32 + (lane & 3) * 8;
    const float4* ap = (const float4*)(a_src1 + base);
    const float4* dp = (const float4*)(a_dst1 + base);
    float4 a0 = ap[0], a1 = ap[1], d0 = dp[0], d1 = dp[1];
    float ps = v0.x*a0.x + v0.y*a0.y + v0.z*a0.z + v0.w*a0.w
             + v1.x*a1.x + v1.y*a1.y + v1.z*a1.z + v1.w*a1.w;
    float pd = v0.x*d0.x + v0.y*d0.y + v0.z*d0.z + v0.w*d0.w
             + v1.x*d1.x + v1.y*d1.y + v1.z*d1.z + v1.w*d1.w;
    ps += __shfl_xor_sync(0xffffffffu, ps, 1);
    ps += __shfl_xor_sync(0xffffffffu, ps, 2);
    pd += __shfl_xor_sync(0xffffffffu, pd, 1);
    pd += __shfl_xor_sync(0xffffffffu, pd, 2);
    if ((lane & 3) == 0) {
        g_as1[w * 8 + h] = ps;
        g_ad1[w * 8 + h] = pd;
    }
}

// ---------------- GAT layer 1 aggregation (warp per dst node) ----------------
__global__ void k_edge1(const float* __restrict__ b1, int N) {
    int w = (blockIdx.x * blockDim.x + threadIdx.x) >> 5;
    int lane = threadIdx.x & 31;
    if (w >= N) return;
    int beg = g_off[w], end = g_off[w + 1];

    // ---- pass A: online softmax stats; 4 edges x 8 heads per iteration
    int h8 = lane & 7;
    float adA = g_ad1[w * 8 + h8];
    float m = -1e30f, ssum = 0.f;
    for (int e = beg + (lane >> 3); e < end; e += 4) {
        int s = g_srcl[e];
        float l = lrelu(g_as1[s * 8 + h8] + adA);
        float nm = fmaxf(m, l);
        ssum = ssum * __expf(m - nm) + __expf(l - nm);
        m = nm;
    }
    // merge lanes with equal (lane&7)
#pragma unroll
    for (int o = 8; o < 32; o <<= 1) {
        float mo = __shfl_xor_sync(0xffffffffu, m, o);
        float so = __shfl_xor_sync(0xffffffffu, ssum, o);
        float nm = fmaxf(m, mo);
        ssum = ssum * __expf(m - nm) + so * __expf(mo - nm);
        m = nm;
    }
    // head for pass B: lane covers cols [lane*8, lane*8+8) -> head = lane>>2
    float mb  = __shfl_sync(0xffffffffu, m,    lane >> 2);
    float sb  = __shfl_sync(0xffffffffu, ssum, lane >> 2);
    float inv = 1.f / sb;
    float adB = g_ad1[w * 8 + (lane >> 2)];

    // ---- pass B: gather h rows, weighted accumulate
    float acc[8] = {};
#pragma unroll 2
    for (int e = beg; e < end; e++) {
        int s = g_srcl[e];
        float l = lrelu(g_as1[s * 8 + (lane >> 2)] + adB);
        float wgt = __expf(l - mb) * inv;
        const float4* hp = (const float4*)(g_h1 + s * 256 + lane * 8);
        float4 v0 = hp[0], v1 = hp[1];
        acc[0] += wgt * v0.x; acc[1] += wgt * v0.y;
        acc[2] += wgt * v0.z; acc[3] += wgt * v0.w;
        acc[4] += wgt * v1.x; acc[5] += wgt * v1.y;
        acc[6] += wgt * v1.z; acc[7] += wgt * v1.w;
    }
    const float4* bp = (const float4*)(b1 + lane * 8);
    float4 bb0 = bp[0], bb1 = bp[1];
    float4 o0, o1;
    o0.x = elu_f(acc[0] + bb0.x); o0.y = elu_f(acc[1] + bb0.y);
    o0.z = elu_f(acc[2] + bb0.z); o0.w = elu_f(acc[3] + bb0.w);
    o1.x = elu_f(acc[4] + bb1.x); o1.y = elu_f(acc[5] + bb1.y);
    o1.z = elu_f(acc[6] + bb1.z); o1.w = elu_f(acc[7] + bb1.w);
    float4* op = (float4*)(g_h1e + w * 256 + lane * 8);
    op[0] = o0; op[1] = o1;
}

// ---------------- mm2: h2 = h1e @ W2 (+ alpha2), 8 nodes / 128-thread block ----
__global__ void k_mm2(const float* __restrict__ W2,
                      const float* __restrict__ a_src2, const float* __restrict__ a_dst2,
                      int N) {
    __shared__ float xs[8][260];           // pad: node stride 4 banks -> conflict free
    __shared__ float W2s[256 * 16];
    int nb = blockIdx.x * 8;
    for (int i = threadIdx.x; i < 4096; i += 128) W2s[i] = W2[i];
    for (int i = threadIdx.x; i < 512; i += 128) {
        int node = i >> 6;
        int c4 = (i & 63);
        int gn = nb + node;
        float4 v = (gn < N) ? ((const float4*)g_h1e)[gn * 64 + c4]
                            : make_float4(0.f, 0.f, 0.f, 0.f);
        xs[node][c4 * 4 + 0] = v.x; xs[node][c4 * 4 + 1] = v.y;
        xs[node][c4 * 4 + 2] = v.z; xs[node][c4 * 4 + 3] = v.w;
    }
    __syncthreads();
    int node = threadIdx.x >> 4, j = threadIdx.x & 15;
    float acc = 0.f;
#pragma unroll 8
    for (int k = 0; k < 256; k++) acc += xs[node][k] * W2s[k * 16 + j];
    float pa = acc * a_src2[j];
    float pd = acc * a_dst2[j];
#pragma unroll
    for (int o = 1; o < 16; o <<= 1) {
        pa += __shfl_xor_sync(0xffffffffu, pa, o);
        pd += __shfl_xor_sync(0xffffffffu, pd, o);
    }
    int gn = nb + node;
    if (gn < N) {
        g_h2[gn * 16 + j] = acc;
        if (j == 0) { g_as2[gn] = pa; g_ad2[gn] = pd; }
    }
}

// ---------------- GAT layer 2 aggregation + elu + fold @W3 (warp per dst) -----
__global__ void k_edge2(const float* __restrict__ b2, const float* __restrict__ W3, int N) {
    int w = (blockIdx.x * blockDim.x + threadIdx.x) >> 5;
    int lane = threadIdx.x & 31;
    if (w >= N) return;
    int beg = g_off[w], end = g_off[w + 1];
    float adv = g_ad2[w];

    // pass A: lane-parallel online softmax (1 head)
    float m = -1e30f, ssum = 0.f;
    for (int e = beg + lane; e < end; e += 32) {
        int s = g_srcl[e];
        float l = lrelu(g_as2[s] + adv);
        float nm = fmaxf(m, l);
        ssum = ssum * __expf(m - nm) + __expf(l - nm);
        m = nm;
    }
#pragma unroll
    for (int o = 1; o < 32; o <<= 1) {
        float mo = __shfl_xor_sync(0xffffffffu, m, o);
        float so = __shfl_xor_sync(0xffffffffu, ssum, o);
        float nm = fmaxf(m, mo);
        ssum = ssum * __expf(m - nm) + so * __expf(mo - nm);
        m = nm;
    }
    float inv = 1.f / ssum;

    // pass B
    float acc = 0.f;
#pragma unroll 2
    for (int e = beg; e < end; e++) {
        int s = g_srcl[e];
        float l = lrelu(g_as2[s] + adv);
        float wgt = __expf(l - m) * inv;
        if (lane < 16) acc += wgt * g_h2[s * 16 + lane];
    }
    float h2e = (lane < 16) ? elu_f(acc + b2[lane]) : 0.f;
    // fold GCN weight: h3 = h2e @ W3 (16x16) via shuffles
    float h3 = 0.f;
#pragma unroll
    for (int k = 0; k < 16; k++) {
        float v = __shfl_sync(0xffffffffu, h2e, k);
        if (lane < 16) h3 += v * W3[k * 16 + lane];
    }
    if (lane < 16) g_h3[w * 16 + lane] = h3;
}

// ---------------- GCN aggregation (warp per dst) ----------------
__global__ void k_gcn(const float* __restrict__ b3, float* __restrict__ out, int N) {
    int w = (blockIdx.x * blockDim.x + threadIdx.x) >> 5;
    int lane = threadIdx.x & 31;
    if (w >= N) return;
    int beg = g_off[w], end = g_off[w + 1];
    float nd = g_dinv[w];
    float acc = 0.f;
#pragma unroll 2
    for (int e = beg; e < end; e++) {
        int s = g_srcl[e];
        float wgt = g_dinv[s] * nd;
        if (lane < 16) acc += wgt * g_h3[s * 16 + lane];
    }
    if (lane < 16) out[w * 16 + lane] = acc + b3[lane];
}

// ---------------- host ----------------
extern "C" void kernel_launch(void* const* d_in, const int* in_sizes, int n_in,
                              void* d_out, int out_size) {
    const float* x     = (const float*)d_in[0];
    const int*   ei    = (const int*)  d_in[1];
    const float* W1    = (const float*)d_in[2];
    const float* as1   = (const float*)d_in[3];
    const float* ad1   = (const float*)d_in[4];
    const float* b1    = (const float*)d_in[5];
    const float* W2    = (const float*)d_in[6];
    const float* as2   = (const float*)d_in[7];
    const float* ad2   = (const float*)d_in[8];
    const float* b2    = (const float*)d_in[9];
    const float* W3    = (const float*)d_in[10];
    const float* b3    = (const float*)d_in[11];
    float* out = (float*)d_out;

    int N = in_sizes[0] / 128;
    int E = in_sizes[1] / 2;
    int Etot = E + N;

    int nB  = (N + 255) / 256;
    int eB  = (Etot + 255) / 256;
    int wB  = (N + 7) / 8;       // warp-per-node kernels, 256 threads

    k_zero_deg<<<nB, 256>>>(N);
    k_hist<<<eB, 256>>>(ei, E, N);
    k_scan<<<1, 1024>>>(N, Etot);
    k_fill<<<eB, 256>>>(ei, E, N);

    dim3 g1(4, (N + BM - 1) / BM);
    k_gemm1<<<g1, 256>>>(x, W1, N);
    k_alpha1<<<wB, 256>>>(as1, ad1, N);
    k_edge1<<<wB, 256>>>(b1, N);
    k_mm2<<<wB, 128>>>(W2, as2, ad2, N);
    k_edge2<<<wB, 256>>>(b2, W3, N);
    k_gcn<<<wB, 256>>>(b3, out, N);
}